// round 2
// baseline (speedup 1.0000x reference)
#include <cuda_runtime.h>
#include <cstdint>
#include <cstddef>

// ---------------------------------------------------------------------------
// MQA: out = softmax((q@Wq) @ (k@Wk)^T / sqrt(64)) @ (v@Wv) @ Wo  (+ biases)
// B=4, S=2048, D_MODEL=1024, H=16, D_K=64, single shared KV head.
// Strategy: tf32 mma.sync (m16n8k8) everywhere, fp32 accumulate.
// ---------------------------------------------------------------------------

#define DEV __device__ __forceinline__

static __device__ float g_qh[8192 * 1024];   // Q projection  [M, 1024]
static __device__ float g_kh[8192 * 64];     // K projection  [M, 64]
static __device__ float g_vh[8192 * 64];     // V projection  [M, 64]
static __device__ float g_attn[8192 * 1024]; // attention out [M, 1024]

DEV unsigned f2tf32(float f) {
    unsigned u;
    asm("cvt.rna.tf32.f32 %0, %1;" : "=r"(u) : "f"(f));
    return u;
}

DEV void mma_tf32(float c[4], const unsigned a[4], const unsigned b[2]) {
    asm volatile(
        "mma.sync.aligned.m16n8k8.row.col.f32.tf32.tf32.f32 "
        "{%0,%1,%2,%3}, {%4,%5,%6,%7}, {%8,%9}, {%0,%1,%2,%3};\n"
        : "+f"(c[0]), "+f"(c[1]), "+f"(c[2]), "+f"(c[3])
        : "r"(a[0]), "r"(a[1]), "r"(a[2]), "r"(a[3]), "r"(b[0]), "r"(b[1]));
}

// ---------------------------------------------------------------------------
// GEMM: C[M,N] = A[M,K] @ W[K,N] + bias.  BM=128, BK=16, BN in {64,128}.
// Block = BN*2 threads. Warp tile = 32x64. Double-buffered smem.
// Smem strides chosen so fragment LDS are bank-conflict-free:
//   A-side stride ≡ 4 (mod 32)  -> bank = 4*g + tg (distinct over warp)
//   B-side stride ≡ 8 (mod 32)  -> bank = 8*tg + g (distinct over warp)
// ---------------------------------------------------------------------------
template <int BN>
__global__ void __launch_bounds__(BN * 2, BN == 64 ? 3 : 2)
gemm_bias_tf32(const float* __restrict__ A, const float* __restrict__ W,
               const float* __restrict__ bias, float* __restrict__ C,
               int M, int N, int K)
{
    constexpr int BM = 128, BK = 16;
    constexpr int NT = BN * 2;
    constexpr int WARPS_N = BN / 64;
    constexpr int SA = BK + 4;   // 20  (20 mod 32 = 20? fragment bank uses row stride: 20*g+tg distinct)
    constexpr int SW = BN + 8;   // 72 / 136, both ≡ 8 (mod 32)

    __shared__ unsigned As[2][BM * SA];
    __shared__ unsigned Ws[2][BK * SW];

    const int tid = threadIdx.x;
    const int warp = tid >> 5;
    const int lane = tid & 31;
    const int g = lane >> 2, tg = lane & 3;
    const int wm = warp / WARPS_N;   // 0..3
    const int wn = warp % WARPS_N;

    const int m0 = blockIdx.y * BM;
    const int n0 = blockIdx.x * BN;

    constexpr int A_PER = (BM * BK / 4) / NT;  // float4 loads per thread
    constexpr int W_PER = (BK * BN / 4) / NT;

    float4 ra[A_PER], rw[W_PER];

    auto ldg_tiles = [&](int k0) {
#pragma unroll
        for (int i = 0; i < A_PER; i++) {
            int idx = tid + i * NT;
            int row = idx >> 2, kq = idx & 3;  // BK/4 = 4 float4 per row
            ra[i] = *(const float4*)(A + (size_t)(m0 + row) * K + k0 + kq * 4);
        }
#pragma unroll
        for (int i = 0; i < W_PER; i++) {
            int idx = tid + i * NT;
            int row = idx / (BN / 4), nq = idx % (BN / 4);
            rw[i] = *(const float4*)(W + (size_t)(k0 + row) * N + n0 + nq * 4);
        }
    };
    auto sts_tiles = [&](int buf) {
#pragma unroll
        for (int i = 0; i < A_PER; i++) {
            int idx = tid + i * NT;
            int row = idx >> 2, kq = idx & 3;
            unsigned* p = &As[buf][row * SA + kq * 4];
            p[0] = f2tf32(ra[i].x); p[1] = f2tf32(ra[i].y);
            p[2] = f2tf32(ra[i].z); p[3] = f2tf32(ra[i].w);
        }
#pragma unroll
        for (int i = 0; i < W_PER; i++) {
            int idx = tid + i * NT;
            int row = idx / (BN / 4), nq = idx % (BN / 4);
            unsigned* p = &Ws[buf][row * SW + nq * 4];
            p[0] = f2tf32(rw[i].x); p[1] = f2tf32(rw[i].y);
            p[2] = f2tf32(rw[i].z); p[3] = f2tf32(rw[i].w);
        }
    };

    float acc[2][8][4] = {};

    ldg_tiles(0);
    sts_tiles(0);
    __syncthreads();

    const int KT = K / BK;
    for (int kt = 0; kt < KT; kt++) {
        if (kt + 1 < KT) ldg_tiles((kt + 1) * BK);
        const int buf = kt & 1;
#pragma unroll
        for (int ks = 0; ks < 2; ks++) {
            unsigned af[2][4], bf[8][2];
#pragma unroll
            for (int mt = 0; mt < 2; mt++) {
                const unsigned* ba = &As[buf][(wm * 32 + mt * 16 + g) * SA + ks * 8 + tg];
                af[mt][0] = ba[0];
                af[mt][1] = ba[8 * SA];
                af[mt][2] = ba[4];
                af[mt][3] = ba[8 * SA + 4];
            }
#pragma unroll
            for (int nt = 0; nt < 8; nt++) {
                const unsigned* bb = &Ws[buf][(ks * 8 + tg) * SW + wn * 64 + nt * 8 + g];
                bf[nt][0] = bb[0];
                bf[nt][1] = bb[4 * SW];
            }
#pragma unroll
            for (int mt = 0; mt < 2; mt++)
#pragma unroll
                for (int nt = 0; nt < 8; nt++)
                    mma_tf32(acc[mt][nt], af[mt], bf[nt]);
        }
        if (kt + 1 < KT) sts_tiles(buf ^ 1);
        __syncthreads();
    }

    // epilogue: + bias, store
#pragma unroll
    for (int mt = 0; mt < 2; mt++) {
        const int row0 = m0 + wm * 32 + mt * 16 + g;
#pragma unroll
        for (int nt = 0; nt < 8; nt++) {
            const int col = n0 + wn * 64 + nt * 8 + tg * 2;
            const float b0 = bias[col], b1 = bias[col + 1];
            float2 v0 = make_float2(acc[mt][nt][0] + b0, acc[mt][nt][1] + b1);
            float2 v1 = make_float2(acc[mt][nt][2] + b0, acc[mt][nt][3] + b1);
            *(float2*)(C + (size_t)row0 * N + col)       = v0;
            *(float2*)(C + (size_t)(row0 + 8) * N + col) = v1;
        }
    }
}

// ---------------------------------------------------------------------------
// Flash attention (MQA): one CTA per (b, h, 128-query tile).
// Q tile [128,64] in smem (pre-scaled by 1/8, tf32). Loop over 64-key tiles:
//   S = Q @ K^T   (tf32 mma, fp32 accum)
//   online softmax (row max/sum via shuffles across the 4-lane quad)
//   P -> smem (warp-private rows, tf32), O += P @ V
// ---------------------------------------------------------------------------
#define FLASH_SMEM 105472

__global__ void __launch_bounds__(128)
mqa_flash(const float* __restrict__ Qh, const float* __restrict__ Kh,
          const float* __restrict__ Vh, float* __restrict__ Out, int S)
{
    constexpr int BQ = 128, BKV = 64, D = 64;
    constexpr int SQ = 68, SK = 68, SV = 72, SP = 68;  // bank-conflict-free strides

    extern __shared__ unsigned sm[];
    unsigned* Qs = sm;                 // 128*68
    unsigned* Ks = Qs + BQ * SQ;       // 64*68
    unsigned* Vs = Ks + BKV * SK;      // 64*72
    unsigned* Ps = Vs + BKV * SV;      // 128*68

    const int tid = threadIdx.x, warp = tid >> 5, lane = tid & 31;
    const int g = lane >> 2, tg = lane & 3;
    const int qt = blockIdx.x, h = blockIdx.y, b = blockIdx.z;

    const float* Qbase = Qh + ((size_t)(b * S + qt * BQ)) * 1024 + h * D;
    const float* Kbase = Kh + (size_t)b * S * D;
    const float* Vbase = Vh + (size_t)b * S * D;
    float* Obase = Out + ((size_t)(b * S + qt * BQ)) * 1024 + h * D;

    const float scale = 0.125f;  // 1/sqrt(64), folded into Q

    // load Q tile (scaled + tf32)
    for (int i = tid; i < BQ * (D / 4); i += 128) {
        int row = i >> 4, q4 = (i & 15) * 4;
        float4 v = *(const float4*)(Qbase + (size_t)row * 1024 + q4);
        unsigned* p = &Qs[row * SQ + q4];
        p[0] = f2tf32(v.x * scale); p[1] = f2tf32(v.y * scale);
        p[2] = f2tf32(v.z * scale); p[3] = f2tf32(v.w * scale);
    }

    float m_r[4], l_r[4];
#pragma unroll
    for (int i = 0; i < 4; i++) { m_r[i] = -1e30f; l_r[i] = 0.f; }
    float oacc[2][8][4] = {};

    const int r0 = warp * 32;  // warp's base row within the Q tile

    for (int j = 0; j < S / BKV; j++) {
        __syncthreads();  // prior tile's smem reads complete (also orders Q load at j=0)
        const float* kp = Kbase + (size_t)j * BKV * D;
        const float* vp = Vbase + (size_t)j * BKV * D;
        for (int i = tid; i < BKV * (D / 4); i += 128) {
            int row = i >> 4, q4 = (i & 15) * 4;
            float4 kv = *(const float4*)(kp + (size_t)row * D + q4);
            unsigned* pk = &Ks[row * SK + q4];
            pk[0] = f2tf32(kv.x); pk[1] = f2tf32(kv.y);
            pk[2] = f2tf32(kv.z); pk[3] = f2tf32(kv.w);
            float4 vv = *(const float4*)(vp + (size_t)row * D + q4);
            unsigned* pv = &Vs[row * SV + q4];
            pv[0] = f2tf32(vv.x); pv[1] = f2tf32(vv.y);
            pv[2] = f2tf32(vv.z); pv[3] = f2tf32(vv.w);
        }
        __syncthreads();

        // ---- S = Q @ K^T ----
        float sacc[2][8][4] = {};
#pragma unroll
        for (int ks = 0; ks < 8; ks++) {
            unsigned af[2][4], bf[8][2];
#pragma unroll
            for (int mt = 0; mt < 2; mt++) {
                const unsigned* ba = &Qs[(r0 + mt * 16 + g) * SQ + ks * 8 + tg];
                af[mt][0] = ba[0];
                af[mt][1] = ba[8 * SQ];
                af[mt][2] = ba[4];
                af[mt][3] = ba[8 * SQ + 4];
            }
#pragma unroll
            for (int nt = 0; nt < 8; nt++) {
                // B(k=d, n=key) = Ks[key][d]
                const unsigned* bb = &Ks[(nt * 8 + g) * SK + ks * 8 + tg];
                bf[nt][0] = bb[0];
                bf[nt][1] = bb[4];
            }
#pragma unroll
            for (int mt = 0; mt < 2; mt++)
#pragma unroll
                for (int nt = 0; nt < 8; nt++)
                    mma_tf32(sacc[mt][nt], af[mt], bf[nt]);
        }

        // ---- online softmax + write P ----
#pragma unroll
        for (int mt = 0; mt < 2; mt++) {
#pragma unroll
            for (int half = 0; half < 2; half++) {
                const int si = half * 2;
                const int ri = mt * 2 + half;
                float mx = -1e30f;
#pragma unroll
                for (int nt = 0; nt < 8; nt++)
                    mx = fmaxf(mx, fmaxf(sacc[mt][nt][si], sacc[mt][nt][si + 1]));
                mx = fmaxf(mx, __shfl_xor_sync(0xffffffffu, mx, 1));
                mx = fmaxf(mx, __shfl_xor_sync(0xffffffffu, mx, 2));
                const float mnew = fmaxf(m_r[ri], mx);
                const float corr = __expf(m_r[ri] - mnew);
                m_r[ri] = mnew;
                float rsum = 0.f;
#pragma unroll
                for (int nt = 0; nt < 8; nt++) {
                    float p0 = __expf(sacc[mt][nt][si] - mnew);
                    float p1 = __expf(sacc[mt][nt][si + 1] - mnew);
                    sacc[mt][nt][si] = p0; sacc[mt][nt][si + 1] = p1;
                    rsum += p0 + p1;
                }
                rsum += __shfl_xor_sync(0xffffffffu, rsum, 1);
                rsum += __shfl_xor_sync(0xffffffffu, rsum, 2);
                l_r[ri] = l_r[ri] * corr + rsum;
#pragma unroll
                for (int nt = 0; nt < 8; nt++) {
                    oacc[mt][nt][si]     *= corr;
                    oacc[mt][nt][si + 1] *= corr;
                }
            }
            // P to smem (warp-private rows; read back as A fragments)
#pragma unroll
            for (int nt = 0; nt < 8; nt++) {
                unsigned* p0 = &Ps[(r0 + mt * 16 + g) * SP + nt * 8 + tg * 2];
                p0[0] = f2tf32(sacc[mt][nt][0]);
                p0[1] = f2tf32(sacc[mt][nt][1]);
                unsigned* p1 = &Ps[(r0 + mt * 16 + g + 8) * SP + nt * 8 + tg * 2];
                p1[0] = f2tf32(sacc[mt][nt][2]);
                p1[1] = f2tf32(sacc[mt][nt][3]);
            }
        }
        __syncwarp();  // order P writes (cross-lane, same warp) before fragment reads

        // ---- O += P @ V ----
#pragma unroll
        for (int ks = 0; ks < 8; ks++) {
            unsigned af[2][4], bf[8][2];
#pragma unroll
            for (int mt = 0; mt < 2; mt++) {
                const unsigned* ba = &Ps[(r0 + mt * 16 + g) * SP + ks * 8 + tg];
                af[mt][0] = ba[0];
                af[mt][1] = ba[8 * SP];
                af[mt][2] = ba[4];
                af[mt][3] = ba[8 * SP + 4];
            }
#pragma unroll
            for (int nt = 0; nt < 8; nt++) {
                // B(k=key, n=d) = Vs[key][d]
                const unsigned* bb = &Vs[(ks * 8 + tg) * SV + nt * 8 + g];
                bf[nt][0] = bb[0];
                bf[nt][1] = bb[4 * SV];
            }
#pragma unroll
            for (int mt = 0; mt < 2; mt++)
#pragma unroll
                for (int nt = 0; nt < 8; nt++)
                    mma_tf32(oacc[mt][nt], af[mt], bf[nt]);
        }
    }

    // ---- epilogue: O /= l, store ----
#pragma unroll
    for (int mt = 0; mt < 2; mt++) {
        const float inv0 = 1.f / l_r[mt * 2 + 0];
        const float inv1 = 1.f / l_r[mt * 2 + 1];
#pragma unroll
        for (int nt = 0; nt < 8; nt++) {
            float2 v0 = make_float2(oacc[mt][nt][0] * inv0, oacc[mt][nt][1] * inv0);
            float2 v1 = make_float2(oacc[mt][nt][2] * inv1, oacc[mt][nt][3] * inv1);
            *(float2*)(Obase + (size_t)(r0 + mt * 16 + g) * 1024 + nt * 8 + tg * 2)     = v0;
            *(float2*)(Obase + (size_t)(r0 + mt * 16 + g + 8) * 1024 + nt * 8 + tg * 2) = v1;
        }
    }
}

// ---------------------------------------------------------------------------
extern "C" void kernel_launch(void* const* d_in, const int* in_sizes, int n_in,
                              void* d_out, int out_size)
{
    const float* q  = (const float*)d_in[0];
    const float* k  = (const float*)d_in[1];
    const float* v  = (const float*)d_in[2];
    const float* Wq = (const float*)d_in[3];
    const float* bq = (const float*)d_in[4];
    const float* Wk = (const float*)d_in[5];
    const float* bk = (const float*)d_in[6];
    const float* Wv = (const float*)d_in[7];
    const float* bv = (const float*)d_in[8];
    const float* Wo = (const float*)d_in[9];
    const float* bo = (const float*)d_in[10];
    float* out = (float*)d_out;

    float *qh, *kh, *vh, *attn;
    cudaGetSymbolAddress((void**)&qh, g_qh);
    cudaGetSymbolAddress((void**)&kh, g_kh);
    cudaGetSymbolAddress((void**)&vh, g_vh);
    cudaGetSymbolAddress((void**)&attn, g_attn);

    const int M = 8192, Dm = 1024, Dk = 64, S = 2048;

    // projections
    gemm_bias_tf32<128><<<dim3(Dm / 128, M / 128), 256>>>(q, Wq, bq, qh, M, Dm, Dm);
    gemm_bias_tf32<64><<<dim3(1, M / 128), 128>>>(k, Wk, bk, kh, M, Dk, Dm);
    gemm_bias_tf32<64><<<dim3(1, M / 128), 128>>>(v, Wv, bv, vh, M, Dk, Dm);

    // attention
    cudaFuncSetAttribute(mqa_flash, cudaFuncAttributeMaxDynamicSharedMemorySize, FLASH_SMEM);
    mqa_flash<<<dim3(S / 128, 16, 4), 128, FLASH_SMEM>>>(qh, kh, vh, attn, S);

    // output projection
    gemm_bias_tf32<128><<<dim3(Dm / 128, M / 128), 256>>>(attn, Wo, bo, out, M, Dm, Dm);
}